// round 1
// baseline (speedup 1.0000x reference)
#include <cuda_runtime.h>
#include <cuda_bf16.h>
#include <cstdint>

#define Hc 4
#define Bc 4
#define Nc 2048
#define Fc 128
#define Uc 64
#define NW (Nc/32)          // 64 words per adjacency row
#define NWP 65              // padded smem stride for bits (bank-conflict-free)
#define TJ 512              // j-tile staged in smem
#define TJP (TJ + 8)        // padded row stride (halves) for proj tile

#define SMEM_MAIN (Nc*4 + 128*NWP*4 + Uc*TJP*2)

// Scratch (device globals; no dynamic allocation allowed)
__device__ float g_s[Hc*Bc*Nc];                                   // 128 KB
__device__ __align__(16) __nv_bfloat16 g_projT[(size_t)Hc*Bc*Uc*Nc]; // 4 MB, [h][b][u][n]
__device__ unsigned g_bits[(size_t)Bc*Nc*NW];                     // 2 MB

// ---------------------------------------------------------------------------
__global__ void k_zero(float* __restrict__ out, int n){
  int i = blockIdx.x*blockDim.x + threadIdx.x;
  if (i < n) out[i] = 0.f;
}

// ---------------------------------------------------------------------------
// Bit-pack adj>0. One thread per element; ballot; lane 0 writes the word.
__global__ void k_bits(const int* __restrict__ adj){
  size_t t = (size_t)blockIdx.x*blockDim.x + threadIdx.x;
  unsigned m = __ballot_sync(0xffffffffu, adj[t] > 0);
  if ((threadIdx.x & 31) == 0) g_bits[t >> 5] = m;
}

// ---------------------------------------------------------------------------
// proj = relu(x @ W[h] + b[h]) ; s = proj . a_w[h] + a_b[h]
// Stores projT bf16 [h][b][u][n] (n contiguous) and s fp32.
// Block: 64 threads (u), handles (h, b, 16 rows).
__global__ void k_proj(const float* __restrict__ x, const float* __restrict__ W,
                       const float* __restrict__ bias, const float* __restrict__ aw,
                       const float* __restrict__ ab){
  __shared__ __align__(16) float xs[16][Fc];
  __shared__ float sred[64][17];
  int nt = blockIdx.x & 127;          // Nc/16 = 128 tiles
  int hb = blockIdx.x >> 7;
  int b = hb & 3, h = hb >> 2;
  int n0 = nt * 16;
  int u = threadIdx.x;

  const float* xp = x + ((size_t)b*Nc + n0)*Fc;
  for (int i = u; i < 16*Fc/4; i += 64)
    ((float4*)xs)[i] = ((const float4*)xp)[i];
  __syncthreads();

  float acc[16];
  float bv = bias[h*Uc + u];
  #pragma unroll
  for (int r = 0; r < 16; r++) acc[r] = bv;

  const float* wp = W + (size_t)h*Fc*Uc + u;
  #pragma unroll 4
  for (int f = 0; f < Fc; f += 4){
    float w0 = wp[(f+0)*Uc], w1 = wp[(f+1)*Uc];
    float w2 = wp[(f+2)*Uc], w3 = wp[(f+3)*Uc];
    #pragma unroll
    for (int r = 0; r < 16; r++){
      float4 xq = *(const float4*)&xs[r][f];
      acc[r] += xq.x*w0 + xq.y*w1 + xq.z*w2 + xq.w*w3;
    }
  }

  float av = aw[h*Uc + u];
  __nv_bfloat16 tmp[16];
  #pragma unroll
  for (int r = 0; r < 16; r++){
    float v = fmaxf(acc[r], 0.f);
    sred[u][r] = v * av;
    tmp[r] = __float2bfloat16(v);
  }
  __nv_bfloat16* pt = g_projT + (((size_t)h*Bc + b)*Uc + u)*Nc + n0;
  *(uint4*)pt       = *(uint4*)tmp;
  *((uint4*)pt + 1) = *((uint4*)(tmp + 8));

  __syncthreads();
  if (u < 16){
    float ssum = ab[h];
    #pragma unroll 8
    for (int t = 0; t < 64; t++) ssum += sred[t][u];
    g_s[((size_t)h*Bc + b)*Nc + n0 + u] = ssum;
  }
}

// ---------------------------------------------------------------------------
// Fused masked-exp softmax-aggregation via mma.sync bf16.
// Block: 256 threads (8 warps), i-tile = 128 rows, warp owns 16 rows x 64 u.
__global__ void __launch_bounds__(256) k_main(float* __restrict__ out){
  extern __shared__ char smem[];
  float*         s_sh    = (float*)smem;                        // Nc floats
  unsigned*      bits_sh = (unsigned*)(smem + Nc*4);            // 128 x NWP
  __nv_bfloat16* pj      = (__nv_bfloat16*)(smem + Nc*4 + 128*NWP*4); // 64 x TJP

  int it = blockIdx.x;        // 0..15
  int b  = blockIdx.y;
  int h  = blockIdx.z;
  int i0 = it * 128;
  int tid  = threadIdx.x;
  int wid  = tid >> 5, lane = tid & 31;
  int g = lane >> 2, c = lane & 3;

  const float* sg = g_s + ((size_t)h*Bc + b)*Nc;
  for (int j = tid; j < Nc; j += 256) s_sh[j] = sg[j];
  const unsigned* bg = g_bits + ((size_t)b*Nc + i0)*NW;
  for (int w = tid; w < 128*NW; w += 256)
    bits_sh[(w/NW)*NWP + (w%NW)] = bg[w];
  __syncthreads();

  int r0 = wid*16 + g;        // local row for frag rows g / g+8
  int r1 = r0 + 8;
  float si0 = s_sh[i0 + r0];
  float si1 = s_sh[i0 + r1];

  float cacc[32];
  #pragma unroll
  for (int q = 0; q < 32; q++) cacc[q] = 0.f;
  float z0 = 0.f, z1 = 0.f;

  const __nv_bfloat16* ptg = g_projT + ((size_t)h*Bc + b)*Uc*Nc;

  for (int jt = 0; jt < Nc; jt += TJ){
    __syncthreads();
    // stage proj tile [64 u][TJ j] (padded stride) — coalesced 16B loads
    for (int idx = tid; idx < Uc*(TJ/8); idx += 256){
      int u = idx >> 6;       // TJ/8 = 64 segments per row
      int seg = idx & 63;
      *(uint4*)(pj + u*TJP + seg*8) =
        *(const uint4*)(ptg + (size_t)u*Nc + jt + seg*8);
    }
    __syncthreads();

    #pragma unroll 2
    for (int k = 0; k < TJ; k += 16){
      int j0 = jt + k;
      unsigned w0 = bits_sh[r0*NWP + (j0 >> 5)] >> (j0 & 31);
      unsigned w1 = bits_sh[r1*NWP + (j0 >> 5)] >> (j0 & 31);
      float2 sjA = *(const float2*)&s_sh[j0 + 2*c];
      float2 sjB = *(const float2*)&s_sh[j0 + 2*c + 8];

      float e00 = ((w0 >> (2*c))   & 1) ? __expf(si0*sjA.x) : 0.f;
      float e01 = ((w0 >> (2*c+1)) & 1) ? __expf(si0*sjA.y) : 0.f;
      float e02 = ((w0 >> (2*c+8)) & 1) ? __expf(si0*sjB.x) : 0.f;
      float e03 = ((w0 >> (2*c+9)) & 1) ? __expf(si0*sjB.y) : 0.f;
      float e10 = ((w1 >> (2*c))   & 1) ? __expf(si1*sjA.x) : 0.f;
      float e11 = ((w1 >> (2*c+1)) & 1) ? __expf(si1*sjA.y) : 0.f;
      float e12 = ((w1 >> (2*c+8)) & 1) ? __expf(si1*sjB.x) : 0.f;
      float e13 = ((w1 >> (2*c+9)) & 1) ? __expf(si1*sjB.y) : 0.f;

      unsigned a0, a1, a2, a3;
      { __nv_bfloat162 t = __floats2bfloat162_rn(e00, e01); a0 = *(unsigned*)&t; }
      { __nv_bfloat162 t = __floats2bfloat162_rn(e10, e11); a1 = *(unsigned*)&t; }
      { __nv_bfloat162 t = __floats2bfloat162_rn(e02, e03); a2 = *(unsigned*)&t; }
      { __nv_bfloat162 t = __floats2bfloat162_rn(e12, e13); a3 = *(unsigned*)&t; }

      // Z from the *rounded* weights (num/denom rounding cancels). bf16->f32 is a shift.
      z0 += __uint_as_float(a0 << 16) + __uint_as_float(a0 & 0xffff0000u)
          + __uint_as_float(a2 << 16) + __uint_as_float(a2 & 0xffff0000u);
      z1 += __uint_as_float(a1 << 16) + __uint_as_float(a1 & 0xffff0000u)
          + __uint_as_float(a3 << 16) + __uint_as_float(a3 & 0xffff0000u);

      #pragma unroll
      for (int t = 0; t < 8; t++){
        const __nv_bfloat16* bp = pj + (t*8 + g)*TJP + k + 2*c;
        unsigned b0 = *(const unsigned*)bp;
        unsigned b1 = *(const unsigned*)(bp + 8);
        float* d = cacc + t*4;
        asm volatile(
          "mma.sync.aligned.m16n8k16.row.col.f32.bf16.bf16.f32 "
          "{%0,%1,%2,%3}, {%4,%5,%6,%7}, {%8,%9}, {%0,%1,%2,%3};\n"
          : "+f"(d[0]), "+f"(d[1]), "+f"(d[2]), "+f"(d[3])
          : "r"(a0), "r"(a1), "r"(a2), "r"(a3), "r"(b0), "r"(b1));
      }
    }
  }

  // Full-row Z: quad lanes (c=0..3) tile the 16 columns of each k-step
  z0 += __shfl_xor_sync(0xffffffffu, z0, 1);
  z0 += __shfl_xor_sync(0xffffffffu, z0, 2);
  z1 += __shfl_xor_sync(0xffffffffu, z1, 1);
  z1 += __shfl_xor_sync(0xffffffffu, z1, 2);
  float inv0 = 1.f / (4.f * z0);   // /Z and /H
  float inv1 = 1.f / (4.f * z1);

  float* o0 = out + ((size_t)b*Nc + i0 + r0)*Uc;
  float* o1 = out + ((size_t)b*Nc + i0 + r1)*Uc;
  #pragma unroll
  for (int t = 0; t < 8; t++){
    int u = t*8 + 2*c;
    atomicAdd(&o0[u],   cacc[t*4+0]*inv0);
    atomicAdd(&o0[u+1], cacc[t*4+1]*inv0);
    atomicAdd(&o1[u],   cacc[t*4+2]*inv1);
    atomicAdd(&o1[u+1], cacc[t*4+3]*inv1);
  }
}

// ---------------------------------------------------------------------------
extern "C" void kernel_launch(void* const* d_in, const int* in_sizes, int n_in,
                              void* d_out, int out_size){
  const float* x    = (const float*)d_in[0];
  const int*   adj  = (const int*)d_in[1];
  const float* W    = (const float*)d_in[2];
  const float* bias = (const float*)d_in[3];
  const float* aw   = (const float*)d_in[4];
  const float* ab   = (const float*)d_in[5];
  float* out = (float*)d_out;

  cudaFuncSetAttribute(k_main, cudaFuncAttributeMaxDynamicSharedMemorySize, SMEM_MAIN);

  k_zero<<<(out_size + 255)/256, 256>>>(out, out_size);
  k_bits<<<(Bc*Nc*Nc)/256, 256>>>(adj);
  k_proj<<<Hc*Bc*(Nc/16), 64>>>(x, W, bias, aw, ab);
  k_main<<<dim3(Nc/128, Bc, Hc), 256, SMEM_MAIN>>>(out);
}

// round 2
// speedup vs baseline: 1.2433x; 1.2433x over previous
#include <cuda_runtime.h>
#include <cuda_bf16.h>
#include <cstdint>

#define Hc 4
#define Bc 4
#define Nc 2048
#define Fc 128
#define Uc 64
#define NW (Nc/32)          // 64 words per adjacency row
#define TJ 512              // j-tile staged in smem
#define TJP (TJ + 8)        // padded row stride (halves): conflict-free ldmatrix

#define SMEM_MAIN (Nc*4 + Uc*TJP*2)   // 8192 + 66560 = 74752 -> 2 blocks/SM

// Scratch (device globals; no dynamic allocation allowed)
__device__ float g_s[Hc*Bc*Nc];                                      // 128 KB
__device__ __align__(16) __nv_bfloat16 g_projT[(size_t)Hc*Bc*Uc*Nc]; // 4 MB, [h][b][u][n]
__device__ unsigned g_bits[(size_t)Bc*Nc*NW];                        // 2 MB

__device__ __forceinline__ float ex2f(float x){
  float y; asm("ex2.approx.f32 %0, %1;" : "=f"(y) : "f"(x)); return y;
}

// ---------------------------------------------------------------------------
// Fused: zero d_out + bit-pack adj>0 (one launch, both DRAM-bound/trivial)
#define ZBLK ((Bc*Nc*Uc)/256)          // 2048 blocks zero the output
__global__ void k_pre(const int* __restrict__ adj, float* __restrict__ out){
  unsigned bid = blockIdx.x;
  if (bid < ZBLK){
    out[bid*256 + threadIdx.x] = 0.f;
  } else {
    size_t t = (size_t)(bid - ZBLK)*256 + threadIdx.x;
    unsigned m = __ballot_sync(0xffffffffu, adj[t] > 0);
    if ((threadIdx.x & 31) == 0) g_bits[t >> 5] = m;
  }
}

// ---------------------------------------------------------------------------
// proj = relu(x @ W[h] + b[h]); s = proj . a_w[h] + a_b[h]
// All 4 heads fused into one 256-column GEMM: block = 32 rows x 256 cols, K=128.
// 256 threads, thread tile 8 rows x 4 cols. x read ONCE. Stores projT bf16
// [h][b][u][n] (n contiguous) + s fp32 (s computed from fp32 proj: accuracy).
#define RB 32
__global__ __launch_bounds__(256) void k_proj(
    const float* __restrict__ x, const float* __restrict__ W,
    const float* __restrict__ bias, const float* __restrict__ aw,
    const float* __restrict__ ab){
  __shared__ float xs[RB*Fc];        // 16 KB
  __shared__ float ws[32*256];       // 32 KB (one 32-f chunk of W', cols = h*64+u)
  int tid = threadIdx.x;
  int cg = tid & 63, rg = tid >> 6;
  int nt = blockIdx.x & 63;          // Nc/RB = 64 row-tiles
  int b  = blockIdx.x >> 6;
  int n0 = nt * RB;
  int h  = cg >> 4;
  int u0 = (cg & 15) * 4;

  // stage x rows once (contiguous 16 KB)
  const float4* xp = (const float4*)(x + ((size_t)b*Nc + n0)*Fc);
  #pragma unroll
  for (int i = 0; i < 4; i++) ((float4*)xs)[tid + i*256] = xp[tid + i*256];

  float4 bv = *(const float4*)&bias[h*Uc + u0];
  float acc[8][4];
  #pragma unroll
  for (int r = 0; r < 8; r++){
    acc[r][0]=bv.x; acc[r][1]=bv.y; acc[r][2]=bv.z; acc[r][3]=bv.w;
  }

  for (int kc = 0; kc < 4; kc++){
    int f0 = kc*32;
    __syncthreads();
    // stage W chunk [32 f][256 cols]
    #pragma unroll
    for (int i = 0; i < 8; i++){
      int idx4 = tid + i*256;                 // float4 index, 2048 total
      int fr = idx4 >> 6, cq = idx4 & 63;     // col quad
      ((float4*)ws)[idx4] =
        *(const float4*)(W + (size_t)(cq>>4)*Fc*Uc + (size_t)(f0+fr)*Uc + (cq&15)*4);
    }
    __syncthreads();
    #pragma unroll 4
    for (int f = 0; f < 32; f++){
      float4 wv = ((const float4*)ws)[f*64 + cg];
      float xv[8];
      #pragma unroll
      for (int r = 0; r < 8; r++) xv[r] = xs[(rg*8+r)*Fc + f0 + f];  // broadcast
      #pragma unroll
      for (int r = 0; r < 8; r++){
        float xr = xv[r];
        acc[r][0] += xr*wv.x; acc[r][1] += xr*wv.y;
        acc[r][2] += xr*wv.z; acc[r][3] += xr*wv.w;
      }
    }
  }

  float4 av = *(const float4*)&aw[h*Uc + u0];
  float aq[4] = {av.x, av.y, av.z, av.w};
  float sp[8];
  #pragma unroll
  for (int r = 0; r < 8; r++) sp[r] = 0.f;

  #pragma unroll
  for (int q = 0; q < 4; q++){
    __nv_bfloat16 tmp[8];
    #pragma unroll
    for (int r = 0; r < 8; r++){
      float v = fmaxf(acc[r][q], 0.f);
      sp[r] += v * aq[q];
      tmp[r] = __float2bfloat16(v);
    }
    *(uint4*)(g_projT + (((size_t)h*Bc + b)*Uc + (u0+q))*Nc + n0 + rg*8) = *(uint4*)tmp;
  }
  // reduce sp over the 16 lanes of this head group (lane groups aligned in warp)
  #pragma unroll
  for (int m = 1; m < 16; m <<= 1){
    #pragma unroll
    for (int r = 0; r < 8; r++) sp[r] += __shfl_xor_sync(0xffffffffu, sp[r], m);
  }
  if ((cg & 15) == 0){
    float abh = ab[h];
    #pragma unroll
    for (int r = 0; r < 8; r++)
      g_s[((size_t)h*Bc + b)*Nc + n0 + rg*8 + r] = sp[r] + abh;
  }
}

// ---------------------------------------------------------------------------
// Fused masked-exp softmax-aggregation via mma.sync bf16 + ldmatrix B-frags.
// Block: 256 threads (8 warps), i-tile 128 rows, warp owns 16 rows x 64 u.
// Z accumulated by an extra MMA against an all-ones B. 2 blocks/SM.
__global__ __launch_bounds__(256, 2) void k_main(float* __restrict__ out){
  extern __shared__ char smem[];
  float*         s_sh = (float*)smem;                    // Nc floats
  __nv_bfloat16* pj   = (__nv_bfloat16*)(smem + Nc*4);   // 64 x TJP halves

  int it = blockIdx.x, b = blockIdx.y, h = blockIdx.z;
  int i0 = it * 128;
  int tid = threadIdx.x, wid = tid >> 5, lane = tid & 31;
  int g = lane >> 2, c = lane & 3;
  int sh0 = 2*c;

  const float* sg = g_s + ((size_t)h*Bc + b)*Nc;
  #pragma unroll
  for (int i = 0; i < 2; i++)
    ((float4*)s_sh)[tid + i*256] = ((const float4*)sg)[tid + i*256];
  __syncthreads();

  int r0 = wid*16 + g;
  float si0l = s_sh[i0 + r0]     * 1.4426950408889634f;
  float si1l = s_sh[i0 + r0 + 8] * 1.4426950408889634f;

  const unsigned* brow0 = g_bits + ((size_t)b*Nc + i0 + r0)*NW;
  const unsigned* brow1 = brow0 + 8*NW;

  // ldmatrix base byte-addresses (4 x4-loads cover B-frags of 8 u-groups)
  unsigned pj_base = (unsigned)__cvta_generic_to_shared(pj);
  unsigned lmaddr[4];
  {
    int q = lane >> 3, i = lane & 7;
    #pragma unroll
    for (int p = 0; p < 4; p++){
      int row  = (2*p + (q>>1))*8 + i;   // u index
      int koff = (q & 1)*8;              // k halves
      lmaddr[p] = pj_base + (unsigned)(row*TJP + koff)*2u;
    }
  }

  float cacc[32];
  #pragma unroll
  for (int i = 0; i < 32; i++) cacc[i] = 0.f;
  float dz[4] = {0.f, 0.f, 0.f, 0.f};
  const unsigned ONES = 0x3F803F80u;     // bf16x2 {1.0, 1.0}

  const __nv_bfloat16* ptg = g_projT + ((size_t)h*Bc + b)*Uc*Nc;

  for (int jt = 0; jt < Nc; jt += TJ){
    __syncthreads();
    // stage proj tile [64 u][TJ j], padded stride; coalesced 16B
    #pragma unroll
    for (int i = 0; i < 16; i++){
      int idx = tid + i*256;             // 4096 uint4
      int u = idx >> 6, seg = idx & 63;
      *(uint4*)(pj + u*TJP + seg*8) = *(const uint4*)(ptg + (size_t)u*Nc + jt + seg*8);
    }
    __syncthreads();

    int wbase = jt >> 5;
    #pragma unroll 1
    for (int q128 = 0; q128 < 4; q128++){
      uint4 bw0 = *(const uint4*)(brow0 + wbase + q128*4);   // row r0 bits (128 j)
      uint4 bw1 = *(const uint4*)(brow1 + wbase + q128*4);   // row r0+8 bits
      #pragma unroll
      for (int w = 0; w < 4; w++){
        unsigned wr0 = (w==0)?bw0.x:(w==1)?bw0.y:(w==2)?bw0.z:bw0.w;
        unsigned wr1 = (w==0)?bw1.x:(w==1)?bw1.y:(w==2)?bw1.z:bw1.w;
        #pragma unroll
        for (int half = 0; half < 2; half++){
          int k  = q128*128 + w*32 + half*16;
          int j0 = jt + k;
          int base = half*16;

          float2 sjA = *(const float2*)&s_sh[j0 + sh0];
          float2 sjB = *(const float2*)&s_sh[j0 + sh0 + 8];

          unsigned t0  = (wr0 >> (base + sh0))     & 3u;
          unsigned t0b = (wr0 >> (base + sh0 + 8)) & 3u;
          unsigned t1  = (wr1 >> (base + sh0))     & 3u;
          unsigned t1b = (wr1 >> (base + sh0 + 8)) & 3u;
          unsigned m0  = (t0 &1u)*0xFFFFu | (t0 &2u)*0x7FFF8000u;
          unsigned m0b = (t0b&1u)*0xFFFFu | (t0b&2u)*0x7FFF8000u;
          unsigned m1  = (t1 &1u)*0xFFFFu | (t1 &2u)*0x7FFF8000u;
          unsigned m1b = (t1b&1u)*0xFFFFu | (t1b&2u)*0x7FFF8000u;

          float e00 = ex2f(si0l*sjA.x), e01 = ex2f(si0l*sjA.y);
          float e02 = ex2f(si0l*sjB.x), e03 = ex2f(si0l*sjB.y);
          float e10 = ex2f(si1l*sjA.x), e11 = ex2f(si1l*sjA.y);
          float e12 = ex2f(si1l*sjB.x), e13 = ex2f(si1l*sjB.y);

          unsigned a0,a1,a2,a3;
          { __nv_bfloat162 t = __floats2bfloat162_rn(e00,e01); a0 = (*(unsigned*)&t) & m0;  }
          { __nv_bfloat162 t = __floats2bfloat162_rn(e10,e11); a1 = (*(unsigned*)&t) & m1;  }
          { __nv_bfloat162 t = __floats2bfloat162_rn(e02,e03); a2 = (*(unsigned*)&t) & m0b; }
          { __nv_bfloat162 t = __floats2bfloat162_rn(e12,e13); a3 = (*(unsigned*)&t) & m1b; }

          unsigned bf[4][4];
          #pragma unroll
          for (int p = 0; p < 4; p++){
            asm volatile("ldmatrix.sync.aligned.m8n8.x4.shared.b16 {%0,%1,%2,%3}, [%4];"
              : "=r"(bf[p][0]), "=r"(bf[p][1]), "=r"(bf[p][2]), "=r"(bf[p][3])
              : "r"(lmaddr[p] + (unsigned)(k*2)));
          }

          // Z: ones-B MMA (row-sums land identically in all 8 columns)
          asm volatile("mma.sync.aligned.m16n8k16.row.col.f32.bf16.bf16.f32 "
            "{%0,%1,%2,%3}, {%4,%5,%6,%7}, {%8,%9}, {%0,%1,%2,%3};"
            : "+f"(dz[0]), "+f"(dz[1]), "+f"(dz[2]), "+f"(dz[3])
            : "r"(a0),"r"(a1),"r"(a2),"r"(a3), "r"(ONES), "r"(ONES));

          #pragma unroll
          for (int t8 = 0; t8 < 8; t8++){
            unsigned bb0 = bf[t8>>1][(t8&1)*2];
            unsigned bb1 = bf[t8>>1][(t8&1)*2 + 1];
            float* d = cacc + t8*4;
            asm volatile("mma.sync.aligned.m16n8k16.row.col.f32.bf16.bf16.f32 "
              "{%0,%1,%2,%3}, {%4,%5,%6,%7}, {%8,%9}, {%0,%1,%2,%3};"
              : "+f"(d[0]), "+f"(d[1]), "+f"(d[2]), "+f"(d[3])
              : "r"(a0),"r"(a1),"r"(a2),"r"(a3), "r"(bb0), "r"(bb1));
          }
        }
      }
    }
  }

  float inv0 = 1.f / (4.f * dz[0]);   // /Z and /H ; all quad lanes identical
  float inv1 = 1.f / (4.f * dz[2]);

  float* o0 = out + ((size_t)b*Nc + i0 + r0)*Uc;
  float* o1 = o0 + 8*Uc;
  #pragma unroll
  for (int t8 = 0; t8 < 8; t8++){
    int u = t8*8 + sh0;
    atomicAdd(&o0[u],   cacc[t8*4+0]*inv0);
    atomicAdd(&o0[u+1], cacc[t8*4+1]*inv0);
    atomicAdd(&o1[u],   cacc[t8*4+2]*inv1);
    atomicAdd(&o1[u+1], cacc[t8*4+3]*inv1);
  }
}

// ---------------------------------------------------------------------------
extern "C" void kernel_launch(void* const* d_in, const int* in_sizes, int n_in,
                              void* d_out, int out_size){
  const float* x    = (const float*)d_in[0];
  const int*   adj  = (const int*)d_in[1];
  const float* W    = (const float*)d_in[2];
  const float* bias = (const float*)d_in[3];
  const float* aw   = (const float*)d_in[4];
  const float* ab   = (const float*)d_in[5];
  float* out = (float*)d_out;

  cudaFuncSetAttribute(k_main, cudaFuncAttributeMaxDynamicSharedMemorySize, SMEM_MAIN);

  k_pre<<<ZBLK + (Bc*Nc*Nc)/256, 256>>>(adj, out);
  k_proj<<<(Nc/RB)*Bc, 256>>>(x, W, bias, aw, ab);
  k_main<<<dim3(Nc/128, Bc, Hc), 256, SMEM_MAIN>>>(out);
}

// round 5
// speedup vs baseline: 1.5961x; 1.2838x over previous
#include <cuda_runtime.h>
#include <cuda_bf16.h>
#include <cstdint>

#define Hc 4
#define Bc 4
#define Nc 2048
#define Fc 128
#define Uc 64
#define NW (Nc/32)          // 64 words per adjacency row
#define TJ 512              // j-tile staged in smem
#define TJP (TJ + 8)        // padded row stride (halves): conflict-free ldmatrix

#define SMEM_MAIN (Nc*4 + Uc*TJP*2)   // 8192 + 66560 = 74752 -> 2 blocks/SM

// Scratch (device globals; no dynamic allocation allowed)
__device__ float g_s[Hc*Bc*Nc];                                      // 128 KB
__device__ __align__(16) __nv_bfloat16 g_projT[(size_t)Hc*Bc*Uc*Nc]; // 4 MB, [h][b][u][n]
__device__ unsigned g_bits[(size_t)Bc*Nc*NW];                        // 2 MB

__device__ __forceinline__ float ex2f(float x){
  float y; asm("ex2.approx.f32 %0, %1;" : "=f"(y) : "f"(x)); return y;
}

// ---------------------------------------------------------------------------
// Fused: zero d_out + bit-pack adj>0.
// Pack path: each lane loads uint4 (4 adj ints = 16B -> 512B/warp per load,
// bandwidth-bound not latency-bound), builds a 4-bit nibble, 3x shfl_xor OR
// assembles element-ordered 32-bit words; one lane per 8 writes the word.
#define ZBLK ((Bc*Nc*Uc)/256)              // 2048 blocks zero the output
#define PBLK ((Bc*Nc*Nc)/(4*256))          // 16384 blocks pack bits
__global__ void k_pre(const int* __restrict__ adj, float* __restrict__ out){
  unsigned bid = blockIdx.x;
  if (bid < ZBLK){
    out[bid*256 + threadIdx.x] = 0.f;
    return;
  }
  size_t q = (size_t)(bid - ZBLK)*256 + threadIdx.x;   // uint4 index
  uint4 v = ((const uint4*)adj)[q];
  unsigned lane = threadIdx.x & 31;
  unsigned nib = (unsigned)(v.x > 0) | ((unsigned)(v.y > 0) << 1)
               | ((unsigned)(v.z > 0) << 2) | ((unsigned)(v.w > 0) << 3);
  unsigned word = nib << (4u*(lane & 7u));
  word |= __shfl_xor_sync(0xffffffffu, word, 1);
  word |= __shfl_xor_sync(0xffffffffu, word, 2);
  word |= __shfl_xor_sync(0xffffffffu, word, 4);
  if ((lane & 7u) == 0) g_bits[q >> 3] = word;
}

// ---------------------------------------------------------------------------
// proj = relu(x @ W[h] + b[h]); s = proj . a_w[h] + a_b[h]
// All 4 heads fused into one 256-column GEMM: block = 32 rows x 256 cols, K=128.
// 256 threads, thread tile 8 rows x 4 cols. x read ONCE. Stores projT bf16
// [h][b][u][n] (n contiguous) + s fp32 (s computed from fp32 proj: accuracy).
#define RB 32
__global__ __launch_bounds__(256) void k_proj(
    const float* __restrict__ x, const float* __restrict__ W,
    const float* __restrict__ bias, const float* __restrict__ aw,
    const float* __restrict__ ab){
  __shared__ float xs[RB*Fc];        // 16 KB
  __shared__ float ws[32*256];       // 32 KB (one 32-f chunk of W', cols = h*64+u)
  int tid = threadIdx.x;
  int cg = tid & 63, rg = tid >> 6;
  int nt = blockIdx.x & 63;          // Nc/RB = 64 row-tiles
  int b  = blockIdx.x >> 6;
  int n0 = nt * RB;
  int h  = cg >> 4;
  int u0 = (cg & 15) * 4;

  // stage x rows once (contiguous 16 KB)
  const float4* xp = (const float4*)(x + ((size_t)b*Nc + n0)*Fc);
  #pragma unroll
  for (int i = 0; i < 4; i++) ((float4*)xs)[tid + i*256] = xp[tid + i*256];

  float4 bv = *(const float4*)&bias[h*Uc + u0];
  float acc[8][4];
  #pragma unroll
  for (int r = 0; r < 8; r++){
    acc[r][0]=bv.x; acc[r][1]=bv.y; acc[r][2]=bv.z; acc[r][3]=bv.w;
  }

  for (int kc = 0; kc < 4; kc++){
    int f0 = kc*32;
    __syncthreads();
    // stage W chunk [32 f][256 cols]
    #pragma unroll
    for (int i = 0; i < 8; i++){
      int idx4 = tid + i*256;                 // float4 index, 2048 total
      int fr = idx4 >> 6, cq = idx4 & 63;     // col quad
      ((float4*)ws)[idx4] =
        *(const float4*)(W + (size_t)(cq>>4)*Fc*Uc + (size_t)(f0+fr)*Uc + (cq&15)*4);
    }
    __syncthreads();
    #pragma unroll 4
    for (int f = 0; f < 32; f++){
      float4 wv = ((const float4*)ws)[f*64 + cg];
      float xv[8];
      #pragma unroll
      for (int r = 0; r < 8; r++) xv[r] = xs[(rg*8+r)*Fc + f0 + f];  // broadcast
      #pragma unroll
      for (int r = 0; r < 8; r++){
        float xr = xv[r];
        acc[r][0] += xr*wv.x; acc[r][1] += xr*wv.y;
        acc[r][2] += xr*wv.z; acc[r][3] += xr*wv.w;
      }
    }
  }

  float4 av = *(const float4*)&aw[h*Uc + u0];
  float aq[4] = {av.x, av.y, av.z, av.w};
  float sp[8];
  #pragma unroll
  for (int r = 0; r < 8; r++) sp[r] = 0.f;

  #pragma unroll
  for (int q = 0; q < 4; q++){
    __nv_bfloat16 tmp[8];
    #pragma unroll
    for (int r = 0; r < 8; r++){
      float v = fmaxf(acc[r][q], 0.f);
      sp[r] += v * aq[q];
      tmp[r] = __float2bfloat16(v);
    }
    *(uint4*)(g_projT + (((size_t)h*Bc + b)*Uc + (u0+q))*Nc + n0 + rg*8) = *(uint4*)tmp;
  }
  // reduce sp over the 16 lanes of this head group (lane groups aligned in warp)
  #pragma unroll
  for (int m = 1; m < 16; m <<= 1){
    #pragma unroll
    for (int r = 0; r < 8; r++) sp[r] += __shfl_xor_sync(0xffffffffu, sp[r], m);
  }
  if ((cg & 15) == 0){
    float abh = ab[h];
    #pragma unroll
    for (int r = 0; r < 8; r++)
      g_s[((size_t)h*Bc + b)*Nc + n0 + rg*8 + r] = sp[r] + abh;
  }
}

// ---------------------------------------------------------------------------
// Fused masked-exp softmax-aggregation via mma.sync bf16 + ldmatrix B-frags.
// Block: 256 threads (8 warps), i-tile 128 rows, warp owns 16 rows x 64 u.
// Z accumulated by an extra MMA against an all-ones B. 2 blocks/SM.
__global__ __launch_bounds__(256, 2) void k_main(float* __restrict__ out){
  extern __shared__ char smem[];
  float*         s_sh = (float*)smem;                    // Nc floats
  __nv_bfloat16* pj   = (__nv_bfloat16*)(smem + Nc*4);   // 64 x TJP halves

  int it = blockIdx.x, b = blockIdx.y, h = blockIdx.z;
  int i0 = it * 128;
  int tid = threadIdx.x, wid = tid >> 5, lane = tid & 31;
  int g = lane >> 2, c = lane & 3;
  int sh0 = 2*c;

  const float* sg = g_s + ((size_t)h*Bc + b)*Nc;
  #pragma unroll
  for (int i = 0; i < 2; i++)
    ((float4*)s_sh)[tid + i*256] = ((const float4*)sg)[tid + i*256];
  __syncthreads();

  int r0 = wid*16 + g;
  float si0l = s_sh[i0 + r0]     * 1.4426950408889634f;
  float si1l = s_sh[i0 + r0 + 8] * 1.4426950408889634f;

  const unsigned* brow0 = g_bits + ((size_t)b*Nc + i0 + r0)*NW;
  const unsigned* brow1 = brow0 + 8*NW;

  // ldmatrix base byte-addresses (4 x4-loads cover B-frags of 8 u-groups)
  unsigned pj_base = (unsigned)__cvta_generic_to_shared(pj);
  unsigned lmaddr[4];
  {
    int q = lane >> 3, i = lane & 7;
    #pragma unroll
    for (int p = 0; p < 4; p++){
      int row  = (2*p + (q>>1))*8 + i;   // u index
      int koff = (q & 1)*8;              // k halves
      lmaddr[p] = pj_base + (unsigned)(row*TJP + koff)*2u;
    }
  }

  float cacc[32];
  #pragma unroll
  for (int i = 0; i < 32; i++) cacc[i] = 0.f;
  float dz[4] = {0.f, 0.f, 0.f, 0.f};
  const unsigned ONES = 0x3F803F80u;     // bf16x2 {1.0, 1.0}

  const __nv_bfloat16* ptg = g_projT + ((size_t)h*Bc + b)*Uc*Nc;

  for (int jt = 0; jt < Nc; jt += TJ){
    __syncthreads();
    // stage proj tile [64 u][TJ j], padded stride; coalesced 16B
    #pragma unroll
    for (int i = 0; i < 16; i++){
      int idx = tid + i*256;             // 4096 uint4
      int u = idx >> 6, seg = idx & 63;
      *(uint4*)(pj + u*TJP + seg*8) = *(const uint4*)(ptg + (size_t)u*Nc + jt + seg*8);
    }
    __syncthreads();

    int wbase = jt >> 5;
    #pragma unroll 1
    for (int q128 = 0; q128 < 4; q128++){
      uint4 bw0 = *(const uint4*)(brow0 + wbase + q128*4);   // row r0 bits (128 j)
      uint4 bw1 = *(const uint4*)(brow1 + wbase + q128*4);   // row r0+8 bits
      #pragma unroll
      for (int w = 0; w < 4; w++){
        unsigned wr0 = (w==0)?bw0.x:(w==1)?bw0.y:(w==2)?bw0.z:bw0.w;
        unsigned wr1 = (w==0)?bw1.x:(w==1)?bw1.y:(w==2)?bw1.z:bw1.w;
        #pragma unroll
        for (int half = 0; half < 2; half++){
          int k  = q128*128 + w*32 + half*16;
          int j0 = jt + k;
          int base = half*16;

          float2 sjA = *(const float2*)&s_sh[j0 + sh0];
          float2 sjB = *(const float2*)&s_sh[j0 + sh0 + 8];

          unsigned t0  = (wr0 >> (base + sh0))     & 3u;
          unsigned t0b = (wr0 >> (base + sh0 + 8)) & 3u;
          unsigned t1  = (wr1 >> (base + sh0))     & 3u;
          unsigned t1b = (wr1 >> (base + sh0 + 8)) & 3u;
          unsigned m0  = (t0 &1u)*0xFFFFu | (t0 &2u)*0x7FFF8000u;
          unsigned m0b = (t0b&1u)*0xFFFFu | (t0b&2u)*0x7FFF8000u;
          unsigned m1  = (t1 &1u)*0xFFFFu | (t1 &2u)*0x7FFF8000u;
          unsigned m1b = (t1b&1u)*0xFFFFu | (t1b&2u)*0x7FFF8000u;

          float e00 = ex2f(si0l*sjA.x), e01 = ex2f(si0l*sjA.y);
          float e02 = ex2f(si0l*sjB.x), e03 = ex2f(si0l*sjB.y);
          float e10 = ex2f(si1l*sjA.x), e11 = ex2f(si1l*sjA.y);
          float e12 = ex2f(si1l*sjB.x), e13 = ex2f(si1l*sjB.y);

          unsigned a0,a1,a2,a3;
          { __nv_bfloat162 t = __floats2bfloat162_rn(e00,e01); a0 = (*(unsigned*)&t) & m0;  }
          { __nv_bfloat162 t = __floats2bfloat162_rn(e10,e11); a1 = (*(unsigned*)&t) & m1;  }
          { __nv_bfloat162 t = __floats2bfloat162_rn(e02,e03); a2 = (*(unsigned*)&t) & m0b; }
          { __nv_bfloat162 t = __floats2bfloat162_rn(e12,e13); a3 = (*(unsigned*)&t) & m1b; }

          unsigned bf[4][4];
          #pragma unroll
          for (int p = 0; p < 4; p++){
            asm volatile("ldmatrix.sync.aligned.m8n8.x4.shared.b16 {%0,%1,%2,%3}, [%4];"
              : "=r"(bf[p][0]), "=r"(bf[p][1]), "=r"(bf[p][2]), "=r"(bf[p][3])
              : "r"(lmaddr[p] + (unsigned)(k*2)));
          }

          // Z: ones-B MMA (row-sums land identically in all 8 columns)
          asm volatile("mma.sync.aligned.m16n8k16.row.col.f32.bf16.bf16.f32 "
            "{%0,%1,%2,%3}, {%4,%5,%6,%7}, {%8,%9}, {%0,%1,%2,%3};"
            : "+f"(dz[0]), "+f"(dz[1]), "+f"(dz[2]), "+f"(dz[3])
            : "r"(a0),"r"(a1),"r"(a2),"r"(a3), "r"(ONES), "r"(ONES));

          #pragma unroll
          for (int t8 = 0; t8 < 8; t8++){
            unsigned bb0 = bf[t8>>1][(t8&1)*2];
            unsigned bb1 = bf[t8>>1][(t8&1)*2 + 1];
            float* d = cacc + t8*4;
            asm volatile("mma.sync.aligned.m16n8k16.row.col.f32.bf16.bf16.f32 "
              "{%0,%1,%2,%3}, {%4,%5,%6,%7}, {%8,%9}, {%0,%1,%2,%3};"
              : "+f"(d[0]), "+f"(d[1]), "+f"(d[2]), "+f"(d[3])
              : "r"(a0),"r"(a1),"r"(a2),"r"(a3), "r"(bb0), "r"(bb1));
          }
        }
      }
    }
  }

  float inv0 = 1.f / (4.f * dz[0]);   // /Z and /H ; all quad lanes identical
  float inv1 = 1.f / (4.f * dz[2]);

  float* o0 = out + ((size_t)b*Nc + i0 + r0)*Uc;
  float* o1 = o0 + 8*Uc;
  #pragma unroll
  for (int t8 = 0; t8 < 8; t8++){
    int u = t8*8 + sh0;
    atomicAdd(&o0[u],   cacc[t8*4+0]*inv0);
    atomicAdd(&o0[u+1], cacc[t8*4+1]*inv0);
    atomicAdd(&o1[u],   cacc[t8*4+2]*inv1);
    atomicAdd(&o1[u+1], cacc[t8*4+3]*inv1);
  }
}

// ---------------------------------------------------------------------------
extern "C" void kernel_launch(void* const* d_in, const int* in_sizes, int n_in,
                              void* d_out, int out_size){
  const float* x    = (const float*)d_in[0];
  const int*   adj  = (const int*)d_in[1];
  const float* W    = (const float*)d_in[2];
  const float* bias = (const float*)d_in[3];
  const float* aw   = (const float*)d_in[4];
  const float* ab   = (const float*)d_in[5];
  float* out = (float*)d_out;

  cudaFuncSetAttribute(k_main, cudaFuncAttributeMaxDynamicSharedMemorySize, SMEM_MAIN);

  k_pre<<<ZBLK + PBLK, 256>>>(adj, out);
  k_proj<<<(Nc/RB)*Bc, 256>>>(x, W, bias, aw, ab);
  k_main<<<dim3(Nc/128, Bc, Hc), 256, SMEM_MAIN>>>(out);
}

// round 6
// speedup vs baseline: 1.6443x; 1.0302x over previous
#include <cuda_runtime.h>
#include <cuda_bf16.h>
#include <cstdint>

#define Hc 4
#define Bc 4
#define Nc 2048
#define Fc 128
#define Uc 64
#define NW (Nc/32)          // 64 words per adjacency row
#define TJ 512              // j-tile staged in smem
#define TJP (TJ + 8)        // padded row stride (halves): conflict-free ldmatrix

#define SMEM_MAIN (Nc*4 + Uc*TJP*2)   // 8192 + 66560 = 74752 -> 2 blocks/SM

// Scratch (device globals; no dynamic allocation allowed)
__device__ float g_s[Hc*Bc*Nc];                                      // 128 KB
__device__ __align__(16) __nv_bfloat16 g_projT[(size_t)Hc*Bc*Uc*Nc]; // 4 MB, [h][b][u][n]
__device__ unsigned g_bits[(size_t)Bc*Nc*NW];                        // 2 MB

__device__ __forceinline__ float ex2f(float x){
  float y; asm("ex2.approx.f32 %0, %1;" : "=f"(y) : "f"(x)); return y;
}

// ---------------------------------------------------------------------------
// ONE prep kernel: proj GEMM blocks first (compute-bound), then output-zeroing
// blocks, then adj bit-pack blocks (DRAM-bound, MLP=2). The scheduler
// co-residents pack blocks with proj blocks -> DRAM streaming hides under FFMA.
#define RB 32
#define PROJB ((Nc/RB)*Bc)                 // 256 proj blocks
#define ZBLK4 ((Bc*Nc*Uc/4)/256)           // 512 zero blocks (float4)
#define PBLK2 ((Bc*Nc*Nc)/(8*256))         // 8192 pack blocks (2 x uint4 / thread)

__global__ __launch_bounds__(256) void k_prep(
    const float* __restrict__ x, const float* __restrict__ W,
    const float* __restrict__ bias, const float* __restrict__ aw,
    const float* __restrict__ ab, const int* __restrict__ adj,
    float* __restrict__ out){
  __shared__ float xs[RB*Fc];        // 16 KB
  __shared__ float ws[32*256];       // 32 KB
  unsigned bid = blockIdx.x;
  int tid = threadIdx.x;

  if (bid >= PROJB){
    unsigned b2 = bid - PROJB;
    if (b2 < ZBLK4){
      ((float4*)out)[(size_t)b2*256 + tid] = make_float4(0.f,0.f,0.f,0.f);
      return;
    }
    // ---- pack path: 512 uint4 (2048 adj elems) per block, 2 loads/thread ----
    size_t q = (size_t)(b2 - ZBLK4)*512 + tid;
    uint4 v0 = ((const uint4*)adj)[q];
    uint4 v1 = ((const uint4*)adj)[q + 256];
    unsigned lane = tid & 31;
    unsigned sh = 4u*(lane & 7u);
    unsigned n0 = (unsigned)(v0.x>0) | ((unsigned)(v0.y>0)<<1)
                | ((unsigned)(v0.z>0)<<2) | ((unsigned)(v0.w>0)<<3);
    unsigned n1 = (unsigned)(v1.x>0) | ((unsigned)(v1.y>0)<<1)
                | ((unsigned)(v1.z>0)<<2) | ((unsigned)(v1.w>0)<<3);
    unsigned w0 = n0 << sh, w1 = n1 << sh;
    w0 |= __shfl_xor_sync(0xffffffffu, w0, 1);
    w1 |= __shfl_xor_sync(0xffffffffu, w1, 1);
    w0 |= __shfl_xor_sync(0xffffffffu, w0, 2);
    w1 |= __shfl_xor_sync(0xffffffffu, w1, 2);
    w0 |= __shfl_xor_sync(0xffffffffu, w0, 4);
    w1 |= __shfl_xor_sync(0xffffffffu, w1, 4);
    if ((lane & 7u) == 0){
      g_bits[q >> 3]        = w0;
      g_bits[(q + 256) >> 3] = w1;
    }
    return;
  }

  // ---- proj path: relu(x@W[h]+b) all 4 heads as one 256-col GEMM ----
  int cg = tid & 63, rg = tid >> 6;
  int nt = bid & 63;
  int b  = bid >> 6;
  int n0 = nt * RB;
  int h  = cg >> 4;
  int u0 = (cg & 15) * 4;

  const float4* xp = (const float4*)(x + ((size_t)b*Nc + n0)*Fc);
  #pragma unroll
  for (int i = 0; i < 4; i++) ((float4*)xs)[tid + i*256] = xp[tid + i*256];

  float4 bv = *(const float4*)&bias[h*Uc + u0];
  float acc[8][4];
  #pragma unroll
  for (int r = 0; r < 8; r++){
    acc[r][0]=bv.x; acc[r][1]=bv.y; acc[r][2]=bv.z; acc[r][3]=bv.w;
  }

  for (int kc = 0; kc < 4; kc++){
    int f0 = kc*32;
    __syncthreads();
    #pragma unroll
    for (int i = 0; i < 8; i++){
      int idx4 = tid + i*256;
      int fr = idx4 >> 6, cq = idx4 & 63;
      ((float4*)ws)[idx4] =
        *(const float4*)(W + (size_t)(cq>>4)*Fc*Uc + (size_t)(f0+fr)*Uc + (cq&15)*4);
    }
    __syncthreads();
    #pragma unroll 4
    for (int f = 0; f < 32; f++){
      float4 wv = ((const float4*)ws)[f*64 + cg];
      float xv[8];
      #pragma unroll
      for (int r = 0; r < 8; r++) xv[r] = xs[(rg*8+r)*Fc + f0 + f];
      #pragma unroll
      for (int r = 0; r < 8; r++){
        float xr = xv[r];
        acc[r][0] += xr*wv.x; acc[r][1] += xr*wv.y;
        acc[r][2] += xr*wv.z; acc[r][3] += xr*wv.w;
      }
    }
  }

  float4 av = *(const float4*)&aw[h*Uc + u0];
  float aq[4] = {av.x, av.y, av.z, av.w};
  float sp[8];
  #pragma unroll
  for (int r = 0; r < 8; r++) sp[r] = 0.f;

  #pragma unroll
  for (int q = 0; q < 4; q++){
    __nv_bfloat16 tmp[8];
    #pragma unroll
    for (int r = 0; r < 8; r++){
      float v = fmaxf(acc[r][q], 0.f);
      sp[r] += v * aq[q];
      tmp[r] = __float2bfloat16(v);
    }
    *(uint4*)(g_projT + (((size_t)h*Bc + b)*Uc + (u0+q))*Nc + n0 + rg*8) = *(uint4*)tmp;
  }
  #pragma unroll
  for (int m = 1; m < 16; m <<= 1){
    #pragma unroll
    for (int r = 0; r < 8; r++) sp[r] += __shfl_xor_sync(0xffffffffu, sp[r], m);
  }
  if ((cg & 15) == 0){
    float abh = ab[h];
    #pragma unroll
    for (int r = 0; r < 8; r++)
      g_s[((size_t)h*Bc + b)*Nc + n0 + rg*8 + r] = sp[r] + abh;
  }
}

// ---------------------------------------------------------------------------
// Fused masked-exp softmax-aggregation via mma.sync bf16 + ldmatrix B-frags.
// Block: 256 threads (8 warps), i-tile 128 rows, warp owns 16 rows x 64 u.
// Z accumulated by an extra MMA against an all-ones B. 2 blocks/SM.
__global__ __launch_bounds__(256, 2) void k_main(float* __restrict__ out){
  extern __shared__ char smem[];
  float*         s_sh = (float*)smem;                    // Nc floats
  __nv_bfloat16* pj   = (__nv_bfloat16*)(smem + Nc*4);   // 64 x TJP halves

  int it = blockIdx.x, b = blockIdx.y, h = blockIdx.z;
  int i0 = it * 128;
  int tid = threadIdx.x, wid = tid >> 5, lane = tid & 31;
  int g = lane >> 2, c = lane & 3;
  int sh0 = 2*c;

  const float* sg = g_s + ((size_t)h*Bc + b)*Nc;
  #pragma unroll
  for (int i = 0; i < 2; i++)
    ((float4*)s_sh)[tid + i*256] = ((const float4*)sg)[tid + i*256];
  __syncthreads();

  int r0 = wid*16 + g;
  float si0l = s_sh[i0 + r0]     * 1.4426950408889634f;
  float si1l = s_sh[i0 + r0 + 8] * 1.4426950408889634f;

  const unsigned* brow0 = g_bits + ((size_t)b*Nc + i0 + r0)*NW;
  const unsigned* brow1 = brow0 + 8*NW;

  unsigned pj_base = (unsigned)__cvta_generic_to_shared(pj);
  unsigned lmaddr[4];
  {
    int q = lane >> 3, i = lane & 7;
    #pragma unroll
    for (int p = 0; p < 4; p++){
      int row  = (2*p + (q>>1))*8 + i;   // u index
      int koff = (q & 1)*8;              // k halves
      lmaddr[p] = pj_base + (unsigned)(row*TJP + koff)*2u;
    }
  }

  float cacc[32];
  #pragma unroll
  for (int i = 0; i < 32; i++) cacc[i] = 0.f;
  float dz[4] = {0.f, 0.f, 0.f, 0.f};
  const unsigned ONES = 0x3F803F80u;     // bf16x2 {1.0, 1.0}

  const __nv_bfloat16* ptg = g_projT + ((size_t)h*Bc + b)*Uc*Nc;

  for (int jt = 0; jt < Nc; jt += TJ){
    __syncthreads();
    #pragma unroll
    for (int i = 0; i < 16; i++){
      int idx = tid + i*256;             // 4096 uint4
      int u = idx >> 6, seg = idx & 63;
      *(uint4*)(pj + u*TJP + seg*8) = *(const uint4*)(ptg + (size_t)u*Nc + jt + seg*8);
    }
    __syncthreads();

    int wbase = jt >> 5;
    #pragma unroll 1
    for (int q128 = 0; q128 < 4; q128++){
      uint4 bw0 = *(const uint4*)(brow0 + wbase + q128*4);
      uint4 bw1 = *(const uint4*)(brow1 + wbase + q128*4);
      #pragma unroll
      for (int w = 0; w < 4; w++){
        unsigned wr0 = (w==0)?bw0.x:(w==1)?bw0.y:(w==2)?bw0.z:bw0.w;
        unsigned wr1 = (w==0)?bw1.x:(w==1)?bw1.y:(w==2)?bw1.z:bw1.w;
        #pragma unroll
        for (int half = 0; half < 2; half++){
          int k  = q128*128 + w*32 + half*16;
          int j0 = jt + k;
          int base = half*16;

          float2 sjA = *(const float2*)&s_sh[j0 + sh0];
          float2 sjB = *(const float2*)&s_sh[j0 + sh0 + 8];

          unsigned t0  = (wr0 >> (base + sh0))     & 3u;
          unsigned t0b = (wr0 >> (base + sh0 + 8)) & 3u;
          unsigned t1  = (wr1 >> (base + sh0))     & 3u;
          unsigned t1b = (wr1 >> (base + sh0 + 8)) & 3u;
          unsigned m0  = (t0 &1u)*0xFFFFu | (t0 &2u)*0x7FFF8000u;
          unsigned m0b = (t0b&1u)*0xFFFFu | (t0b&2u)*0x7FFF8000u;
          unsigned m1  = (t1 &1u)*0xFFFFu | (t1 &2u)*0x7FFF8000u;
          unsigned m1b = (t1b&1u)*0xFFFFu | (t1b&2u)*0x7FFF8000u;

          float e00 = ex2f(si0l*sjA.x), e01 = ex2f(si0l*sjA.y);
          float e02 = ex2f(si0l*sjB.x), e03 = ex2f(si0l*sjB.y);
          float e10 = ex2f(si1l*sjA.x), e11 = ex2f(si1l*sjA.y);
          float e12 = ex2f(si1l*sjB.x), e13 = ex2f(si1l*sjB.y);

          unsigned a0,a1,a2,a3;
          { __nv_bfloat162 t = __floats2bfloat162_rn(e00,e01); a0 = (*(unsigned*)&t) & m0;  }
          { __nv_bfloat162 t = __floats2bfloat162_rn(e10,e11); a1 = (*(unsigned*)&t) & m1;  }
          { __nv_bfloat162 t = __floats2bfloat162_rn(e02,e03); a2 = (*(unsigned*)&t) & m0b; }
          { __nv_bfloat162 t = __floats2bfloat162_rn(e12,e13); a3 = (*(unsigned*)&t) & m1b; }

          unsigned bf[4][4];
          #pragma unroll
          for (int p = 0; p < 4; p++){
            asm volatile("ldmatrix.sync.aligned.m8n8.x4.shared.b16 {%0,%1,%2,%3}, [%4];"
              : "=r"(bf[p][0]), "=r"(bf[p][1]), "=r"(bf[p][2]), "=r"(bf[p][3])
              : "r"(lmaddr[p] + (unsigned)(k*2)));
          }

          asm volatile("mma.sync.aligned.m16n8k16.row.col.f32.bf16.bf16.f32 "
            "{%0,%1,%2,%3}, {%4,%5,%6,%7}, {%8,%9}, {%0,%1,%2,%3};"
            : "+f"(dz[0]), "+f"(dz[1]), "+f"(dz[2]), "+f"(dz[3])
            : "r"(a0),"r"(a1),"r"(a2),"r"(a3), "r"(ONES), "r"(ONES));

          #pragma unroll
          for (int t8 = 0; t8 < 8; t8++){
            unsigned bb0 = bf[t8>>1][(t8&1)*2];
            unsigned bb1 = bf[t8>>1][(t8&1)*2 + 1];
            float* d = cacc + t8*4;
            asm volatile("mma.sync.aligned.m16n8k16.row.col.f32.bf16.bf16.f32 "
              "{%0,%1,%2,%3}, {%4,%5,%6,%7}, {%8,%9}, {%0,%1,%2,%3};"
              : "+f"(d[0]), "+f"(d[1]), "+f"(d[2]), "+f"(d[3])
              : "r"(a0),"r"(a1),"r"(a2),"r"(a3), "r"(bb0), "r"(bb1));
          }
        }
      }
    }
  }

  float inv0 = 1.f / (4.f * dz[0]);   // /Z and /H ; all quad lanes identical
  float inv1 = 1.f / (4.f * dz[2]);

  float* o0 = out + ((size_t)b*Nc + i0 + r0)*Uc;
  float* o1 = o0 + 8*Uc;
  #pragma unroll
  for (int t8 = 0; t8 < 8; t8++){
    int u = t8*8 + sh0;
    atomicAdd(&o0[u],   cacc[t8*4+0]*inv0);
    atomicAdd(&o0[u+1], cacc[t8*4+1]*inv0);
    atomicAdd(&o1[u],   cacc[t8*4+2]*inv1);
    atomicAdd(&o1[u+1], cacc[t8*4+3]*inv1);
  }
}

// ---------------------------------------------------------------------------
extern "C" void kernel_launch(void* const* d_in, const int* in_sizes, int n_in,
                              void* d_out, int out_size){
  const float* x    = (const float*)d_in[0];
  const int*   adj  = (const int*)d_in[1];
  const float* W    = (const float*)d_in[2];
  const float* bias = (const float*)d_in[3];
  const float* aw   = (const float*)d_in[4];
  const float* ab   = (const float*)d_in[5];
  float* out = (float*)d_out;

  cudaFuncSetAttribute(k_main, cudaFuncAttributeMaxDynamicSharedMemorySize, SMEM_MAIN);

  k_prep<<<PROJB + ZBLK4 + PBLK2, 256>>>(x, W, bias, aw, ab, adj, out);
  k_main<<<dim3(Nc/128, Bc, Hc), 256, SMEM_MAIN>>>(out);
}

// round 11
// speedup vs baseline: 1.7007x; 1.0343x over previous
#include <cuda_runtime.h>
#include <cuda_bf16.h>
#include <cstdint>

#define Hc 4
#define Bc 4
#define Nc 2048
#define Fc 128
#define Uc 64
#define NW (Nc/32)          // 64 words per adjacency row
#define TJ 512              // j-tile staged in smem
#define TJP (TJ + 8)        // padded row stride (halves): conflict-free ldmatrix

#define SMEM_MAIN (Nc*4 + Uc*TJP*2)   // 8192 + 66560 = 74752 -> 2 blocks/SM

// Scratch (device globals; no dynamic allocation allowed)
__device__ float g_s[Hc*Bc*Nc];                                      // 128 KB
__device__ __align__(16) __nv_bfloat16 g_projT[(size_t)Hc*Bc*Uc*Nc]; // 4 MB, [h][b][u][n]
__device__ unsigned g_bits[(size_t)Bc*Nc*NW];                        // 2 MB

__device__ __forceinline__ float ex2f(float x){
  float y; asm("ex2.approx.f32 %0, %1;" : "=f"(y) : "f"(x)); return y;
}

// ---------------------------------------------------------------------------
// ONE prep kernel: proj GEMM blocks first (compute-bound), then output-zeroing
// blocks, then adj bit-pack blocks (DRAM-bound, MLP=4 -> 64B in flight/thread).
#define RB 32
#define PROJB ((Nc/RB)*Bc)                 // 256 proj blocks
#define ZBLK4 ((Bc*Nc*Uc/4)/256)           // 512 zero blocks (float4)
#define PBLK4 ((Bc*Nc*Nc)/(16*256))        // 4096 pack blocks (4 x uint4 / thread)

__global__ __launch_bounds__(256) void k_prep(
    const float* __restrict__ x, const float* __restrict__ W,
    const float* __restrict__ bias, const float* __restrict__ aw,
    const float* __restrict__ ab, const int* __restrict__ adj,
    float* __restrict__ out){
  __shared__ float xs[RB*Fc];        // 16 KB
  __shared__ float ws[32*256];       // 32 KB
  unsigned bid = blockIdx.x;
  int tid = threadIdx.x;

  if (bid >= PROJB){
    unsigned b2 = bid - PROJB;
    if (b2 < ZBLK4){
      ((float4*)out)[(size_t)b2*256 + tid] = make_float4(0.f,0.f,0.f,0.f);
      return;
    }
    // ---- pack path: 1024 uint4 (4096 adj elems) per block, 4 loads/thread ----
    size_t q = (size_t)(b2 - ZBLK4)*1024 + tid;
    uint4 v0 = ((const uint4*)adj)[q];
    uint4 v1 = ((const uint4*)adj)[q + 256];
    uint4 v2 = ((const uint4*)adj)[q + 512];
    uint4 v3 = ((const uint4*)adj)[q + 768];
    unsigned lane = tid & 31;
    unsigned sh = 4u*(lane & 7u);
    unsigned w0 = ((unsigned)(v0.x>0) | ((unsigned)(v0.y>0)<<1)
                | ((unsigned)(v0.z>0)<<2) | ((unsigned)(v0.w>0)<<3)) << sh;
    unsigned w1 = ((unsigned)(v1.x>0) | ((unsigned)(v1.y>0)<<1)
                | ((unsigned)(v1.z>0)<<2) | ((unsigned)(v1.w>0)<<3)) << sh;
    unsigned w2 = ((unsigned)(v2.x>0) | ((unsigned)(v2.y>0)<<1)
                | ((unsigned)(v2.z>0)<<2) | ((unsigned)(v2.w>0)<<3)) << sh;
    unsigned w3 = ((unsigned)(v3.x>0) | ((unsigned)(v3.y>0)<<1)
                | ((unsigned)(v3.z>0)<<2) | ((unsigned)(v3.w>0)<<3)) << sh;
    #pragma unroll
    for (int m = 1; m <= 4; m <<= 1){
      w0 |= __shfl_xor_sync(0xffffffffu, w0, m);
      w1 |= __shfl_xor_sync(0xffffffffu, w1, m);
      w2 |= __shfl_xor_sync(0xffffffffu, w2, m);
      w3 |= __shfl_xor_sync(0xffffffffu, w3, m);
    }
    if ((lane & 7u) == 0){
      g_bits[ q        >> 3] = w0;
      g_bits[(q + 256) >> 3] = w1;
      g_bits[(q + 512) >> 3] = w2;
      g_bits[(q + 768) >> 3] = w3;
    }
    return;
  }

  // ---- proj path: relu(x@W[h]+b) all 4 heads as one 256-col GEMM ----
  int cg = tid & 63, rg = tid >> 6;
  int nt = bid & 63;
  int b  = bid >> 6;
  int n0 = nt * RB;
  int h  = cg >> 4;
  int u0 = (cg & 15) * 4;

  const float4* xp = (const float4*)(x + ((size_t)b*Nc + n0)*Fc);
  #pragma unroll
  for (int i = 0; i < 4; i++) ((float4*)xs)[tid + i*256] = xp[tid + i*256];

  float4 bv = *(const float4*)&bias[h*Uc + u0];
  float acc[8][4];
  #pragma unroll
  for (int r = 0; r < 8; r++){
    acc[r][0]=bv.x; acc[r][1]=bv.y; acc[r][2]=bv.z; acc[r][3]=bv.w;
  }

  for (int kc = 0; kc < 4; kc++){
    int f0 = kc*32;
    __syncthreads();
    #pragma unroll
    for (int i = 0; i < 8; i++){
      int idx4 = tid + i*256;
      int fr = idx4 >> 6, cq = idx4 & 63;
      ((float4*)ws)[idx4] =
        *(const float4*)(W + (size_t)(cq>>4)*Fc*Uc + (size_t)(f0+fr)*Uc + (cq&15)*4);
    }
    __syncthreads();
    #pragma unroll 4
    for (int f = 0; f < 32; f++){
      float4 wv = ((const float4*)ws)[f*64 + cg];
      float xv[8];
      #pragma unroll
      for (int r = 0; r < 8; r++) xv[r] = xs[(rg*8+r)*Fc + f0 + f];
      #pragma unroll
      for (int r = 0; r < 8; r++){
        float xr = xv[r];
        acc[r][0] += xr*wv.x; acc[r][1] += xr*wv.y;
        acc[r][2] += xr*wv.z; acc[r][3] += xr*wv.w;
      }
    }
  }

  float4 av = *(const float4*)&aw[h*Uc + u0];
  float aq[4] = {av.x, av.y, av.z, av.w};
  float sp[8];
  #pragma unroll
  for (int r = 0; r < 8; r++) sp[r] = 0.f;

  #pragma unroll
  for (int q = 0; q < 4; q++){
    __nv_bfloat16 tmp[8];
    #pragma unroll
    for (int r = 0; r < 8; r++){
      float v = fmaxf(acc[r][q], 0.f);
      sp[r] += v * aq[q];
      tmp[r] = __float2bfloat16(v);
    }
    *(uint4*)(g_projT + (((size_t)h*Bc + b)*Uc + (u0+q))*Nc + n0 + rg*8) = *(uint4*)tmp;
  }
  #pragma unroll
  for (int m = 1; m < 16; m <<= 1){
    #pragma unroll
    for (int r = 0; r < 8; r++) sp[r] += __shfl_xor_sync(0xffffffffu, sp[r], m);
  }
  if ((cg & 15) == 0){
    float abh = ab[h];
    #pragma unroll
    for (int r = 0; r < 8; r++)
      g_s[((size_t)h*Bc + b)*Nc + n0 + rg*8 + r] = sp[r] + abh;
  }
}

// ---------------------------------------------------------------------------
// Fused masked-exp softmax-aggregation via mma.sync bf16 + ldmatrix B-frags.
// Masking: bit-word shifted once per 32 j, then constant-mask predicated
// zeroing of exp values (LOP3.P + FSEL per element) before bf16 packing.
__global__ __launch_bounds__(256, 2) void k_main(float* __restrict__ out){
  extern __shared__ char smem[];
  float*         s_sh = (float*)smem;                    // Nc floats
  __nv_bfloat16* pj   = (__nv_bfloat16*)(smem + Nc*4);   // 64 x TJP halves

  int it = blockIdx.x, b = blockIdx.y, h = blockIdx.z;
  int i0 = it * 128;
  int tid = threadIdx.x, wid = tid >> 5, lane = tid & 31;
  int g = lane >> 2, c = lane & 3;
  int sh0 = 2*c;

  const float* sg = g_s + ((size_t)h*Bc + b)*Nc;
  #pragma unroll
  for (int i = 0; i < 2; i++)
    ((float4*)s_sh)[tid + i*256] = ((const float4*)sg)[tid + i*256];
  __syncthreads();

  int r0 = wid*16 + g;
  float si0l = s_sh[i0 + r0]     * 1.4426950408889634f;
  float si1l = s_sh[i0 + r0 + 8] * 1.4426950408889634f;

  const unsigned* brow0 = g_bits + ((size_t)b*Nc + i0 + r0)*NW;
  const unsigned* brow1 = brow0 + 8*NW;

  unsigned pj_base = (unsigned)__cvta_generic_to_shared(pj);
  unsigned lmaddr[4];
  {
    int q = lane >> 3, i = lane & 7;
    #pragma unroll
    for (int p = 0; p < 4; p++){
      int row  = (2*p + (q>>1))*8 + i;   // u index
      int koff = (q & 1)*8;              // k halves
      lmaddr[p] = pj_base + (unsigned)(row*TJP + koff)*2u;
    }
  }

  float cacc[32];
  #pragma unroll
  for (int i = 0; i < 32; i++) cacc[i] = 0.f;
  float dz[4] = {0.f, 0.f, 0.f, 0.f};
  const unsigned ONES = 0x3F803F80u;     // bf16x2 {1.0, 1.0}

  const __nv_bfloat16* ptg = g_projT + ((size_t)h*Bc + b)*Uc*Nc;

  for (int jt = 0; jt < Nc; jt += TJ){
    __syncthreads();
    #pragma unroll
    for (int i = 0; i < 16; i++){
      int idx = tid + i*256;             // 4096 uint4
      int u = idx >> 6, seg = idx & 63;
      *(uint4*)(pj + u*TJP + seg*8) = *(const uint4*)(ptg + (size_t)u*Nc + jt + seg*8);
    }
    __syncthreads();

    int wbase = jt >> 5;
    #pragma unroll 1
    for (int q128 = 0; q128 < 4; q128++){
      uint4 bw0 = *(const uint4*)(brow0 + wbase + q128*4);
      uint4 bw1 = *(const uint4*)(brow1 + wbase + q128*4);
      #pragma unroll
      for (int w = 0; w < 4; w++){
        unsigned wr0 = (w==0)?bw0.x:(w==1)?bw0.y:(w==2)?bw0.z:bw0.w;
        unsigned wr1 = (w==0)?bw1.x:(w==1)?bw1.y:(w==2)?bw1.z:bw1.w;
        // one runtime shift per 32 j; all bit tests below use constant masks
        unsigned wrs0 = wr0 >> sh0;
        unsigned wrs1 = wr1 >> sh0;
        #pragma unroll
        for (int half = 0; half < 2; half++){
          const unsigned B0 = 1u << (half*16), B1 = 2u << (half*16);
          const unsigned B8 = 256u << (half*16), B9 = 512u << (half*16);
          int k  = q128*128 + w*32 + half*16;
          int j0 = jt + k;

          float2 sjA = *(const float2*)&s_sh[j0 + sh0];
          float2 sjB = *(const float2*)&s_sh[j0 + sh0 + 8];

          float e00 = ex2f(si0l*sjA.x), e01 = ex2f(si0l*sjA.y);
          float e02 = ex2f(si0l*sjB.x), e03 = ex2f(si0l*sjB.y);
          float e10 = ex2f(si1l*sjA.x), e11 = ex2f(si1l*sjA.y);
          float e12 = ex2f(si1l*sjB.x), e13 = ex2f(si1l*sjB.y);

          if (!(wrs0 & B0)) e00 = 0.f;
          if (!(wrs0 & B1)) e01 = 0.f;
          if (!(wrs0 & B8)) e02 = 0.f;
          if (!(wrs0 & B9)) e03 = 0.f;
          if (!(wrs1 & B0)) e10 = 0.f;
          if (!(wrs1 & B1)) e11 = 0.f;
          if (!(wrs1 & B8)) e12 = 0.f;
          if (!(wrs1 & B9)) e13 = 0.f;

          unsigned a0,a1,a2,a3;
          { __nv_bfloat162 t = __floats2bfloat162_rn(e00,e01); a0 = *(unsigned*)&t; }
          { __nv_bfloat162 t = __floats2bfloat162_rn(e10,e11); a1 = *(unsigned*)&t; }
          { __nv_bfloat162 t = __floats2bfloat162_rn(e02,e03); a2 = *(unsigned*)&t; }
          { __nv_bfloat162 t = __floats2bfloat162_rn(e12,e13); a3 = *(unsigned*)&t; }

          unsigned bf[4][4];
          #pragma unroll
          for (int p = 0; p < 4; p++){
            asm volatile("ldmatrix.sync.aligned.m8n8.x4.shared.b16 {%0,%1,%2,%3}, [%4];"
              : "=r"(bf[p][0]), "=r"(bf[p][1]), "=r"(bf[p][2]), "=r"(bf[p][3])
              : "r"(lmaddr[p] + (unsigned)(k*2)));
          }

          asm volatile("mma.sync.aligned.m16n8k16.row.col.f32.bf16.bf16.f32 "
            "{%0,%1,%2,%3}, {%4,%5,%6,%7}, {%8,%9}, {%0,%1,%2,%3};"
            : "+f"(dz[0]), "+f"(dz[1]), "+f"(dz[2]), "+f"(dz[3])
            : "r"(a0),"r"(a1),"r"(a2),"r"(a3), "r"(ONES), "r"(ONES));

          #pragma unroll
          for (int t8 = 0; t8 < 8; t8++){
            unsigned bb0 = bf[t8>>1][(t8&1)*2];
            unsigned bb1 = bf[t8>>1][(t8&1)*2 + 1];
            float* d = cacc + t8*4;
            asm volatile("mma.sync.aligned.m16n8k16.row.col.f32.bf16.bf16.f32 "
              "{%0,%1,%2,%3}, {%4,%5,%6,%7}, {%8,%9}, {%0,%1,%2,%3};"
              : "+f"(d[0]), "+f"(d[1]), "+f"(d[2]), "+f"(d[3])
              : "r"(a0),"r"(a1),"r"(a2),"r"(a3), "r"(bb0), "r"(bb1));
          }
        }
      }
    }
  }

  float inv0 = 1.f / (4.f * dz[0]);   // /Z and /H ; all quad lanes identical
  float inv1 = 1.f / (4.f * dz[2]);

  float* o0 = out + ((size_t)b*Nc + i0 + r0)*Uc;
  float* o1 = o0 + 8*Uc;
  #pragma unroll
  for (int t8 = 0; t8 < 8; t8++){
    int u = t8*8 + sh0;
    atomicAdd(&o0[u],   cacc[t8*4+0]*inv0);
    atomicAdd(&o0[u+1], cacc[t8*4+1]*inv0);
    atomicAdd(&o1[u],   cacc[t8*4+2]*inv1);
    atomicAdd(&o1[u+1], cacc[t8*4+3]*inv1);
  }
}

// ---------------------------------------------------------------------------
extern "C" void kernel_launch(void* const* d_in, const int* in_sizes, int n_in,
                              void* d_out, int out_size){
  const float* x    = (const float*)d_in[0];
  const int*   adj  = (const int*)d_in[1];
  const float* W    = (const float*)d_in[2];
  const float* bias = (const float*)d_in[3];
  const float* aw   = (const float*)d_in[4];
  const float* ab   = (const float*)d_in[5];
  float* out = (float*)d_out;

  cudaFuncSetAttribute(k_main, cudaFuncAttributeMaxDynamicSharedMemorySize, SMEM_MAIN);

  k_prep<<<PROJB + ZBLK4 + PBLK4, 256>>>(x, W, bias, aw, ab, adj, out);
  k_main<<<dim3(Nc/128, Bc, Hc), 256, SMEM_MAIN>>>(out);
}